// round 12
// baseline (speedup 1.0000x reference)
#include <cuda_runtime.h>
#include <cuda_fp16.h>
#include <math.h>
#include <stdint.h>

// ---------------------------------------------------------------------------
// Problem constants
// ---------------------------------------------------------------------------
#define BB       256
#define DIM      32768
#define SPLITS   32
#define CHUNK    (DIM / SPLITS)     // 1024 fp16 cols per split
#define KB       64                 // k-block = 128 B/row
#define WPC      (CHUNK / KB)       // 16 k-blocks per CTA
#define NCTA     128                // 32 splits x 4 tiles; 1 CTA/SM -> co-resident
#define STRIDE   144                // smem row stride (128 B data + 16 B pad)
#define TILE_SM  (128 * STRIDE)
#define STAGE    (2 * TILE_SM)
#define NSTAGE   3
#define SMEM_TOTAL (NSTAGE * STAGE) // 110592 B
#define MARGIN   0.003f

// ---------------------------------------------------------------------------
// Static device scratch (no allocations anywhere)
// ---------------------------------------------------------------------------
__device__ __align__(16) __half g_h[BB * DIM];       // 16 MB fp16 copy of X
__device__ float  g_part[SPLITS * BB * BB];          // 8 MB split-K partials (full G)
__device__ float  g_sqp[4096];                       // per-K1-block sum-of-squares partials
__device__ double g_lossp[NCTA];
__device__ double g_cntp[NCTA];
__device__ int    g_sync1;
__device__ int    g_elect;

// ---------------------------------------------------------------------------
// Helpers
// ---------------------------------------------------------------------------
__device__ __forceinline__ uint32_t smem_u32(const void* p) {
    uint32_t a;
    asm("{ .reg .u64 t; cvta.to.shared.u64 t, %1; cvt.u32.u64 %0, t; }" : "=r"(a) : "l"(p));
    return a;
}
__device__ __forceinline__ void cpasync16(uint32_t s, const void* g) {
    asm volatile("cp.async.cg.shared.global [%0], [%1], 16;" :: "r"(s), "l"(g) : "memory");
}
__device__ __forceinline__ void ldm_x4(uint32_t a, uint32_t& r0, uint32_t& r1,
                                       uint32_t& r2, uint32_t& r3) {
    asm volatile("ldmatrix.sync.aligned.m8n8.x4.shared.b16 {%0,%1,%2,%3}, [%4];"
                 : "=r"(r0), "=r"(r1), "=r"(r2), "=r"(r3) : "r"(a));
}
__device__ __forceinline__ void mma16816(float& c0, float& c1, float& c2, float& c3,
                                         uint32_t a0, uint32_t a1, uint32_t a2, uint32_t a3,
                                         uint32_t b0, uint32_t b1) {
    asm volatile(
        "mma.sync.aligned.m16n8k16.row.col.f32.f16.f16.f32 "
        "{%0,%1,%2,%3}, {%4,%5,%6,%7}, {%8,%9}, {%0,%1,%2,%3};"
        : "+f"(c0), "+f"(c1), "+f"(c2), "+f"(c3)
        : "r"(a0), "r"(a1), "r"(a2), "r"(a3), "r"(b0), "r"(b1));
}

// ---------------------------------------------------------------------------
// Kernel 1: fp32 -> fp16 convert + per-block sum-of-squares partial.
// Block b covers 2048 contiguous elements of row b/16 (part b%16).
// Also resets the K2 sync/election counters (stream order guarantees this
// completes before K2 starts).
// ---------------------------------------------------------------------------
__global__ __launch_bounds__(256) void convert_kernel(const float* __restrict__ X) {
    const int b   = blockIdx.x;
    const int t   = threadIdx.x;
    const int gid = b * 256 + t;
    __shared__ float warr[8];

    const float4* s = reinterpret_cast<const float4*>(X) + (size_t)gid * 2;
    const float4 a = s[0];
    const float4 c = s[1];
    __half2 h0 = __floats2half2_rn(a.x, a.y);
    __half2 h1 = __floats2half2_rn(a.z, a.w);
    __half2 h2 = __floats2half2_rn(c.x, c.y);
    __half2 h3 = __floats2half2_rn(c.z, c.w);
    uint4 v;
    v.x = *reinterpret_cast<uint32_t*>(&h0);
    v.y = *reinterpret_cast<uint32_t*>(&h1);
    v.z = *reinterpret_cast<uint32_t*>(&h2);
    v.w = *reinterpret_cast<uint32_t*>(&h3);
    reinterpret_cast<uint4*>(g_h)[gid] = v;

    // exact fp32 sum of squares for this thread's 8 elements
    float sq = a.x * a.x + a.y * a.y + a.z * a.z + a.w * a.w
             + c.x * c.x + c.y * c.y + c.z * c.z + c.w * c.w;
#pragma unroll
    for (int o = 16; o > 0; o >>= 1) sq += __shfl_xor_sync(0xFFFFFFFFu, sq, o);
    if ((t & 31) == 0) warr[t >> 5] = sq;
    __syncthreads();
    if (t == 0) {
        float ssum = 0.f;
#pragma unroll
        for (int i = 0; i < 8; i++) ssum += warr[i];
        g_sqp[b] = ssum;
    }
    if (b == 0 && t == 0) { g_sync1 = 0; g_elect = 0; }
}

// ---------------------------------------------------------------------------
// Kernel 2 (fused): full-G split-K fp16 GEMM -> grid spin-sync -> loss.
//   Phase 1: bid -> split = bid&31, tile = bid>>5 (mt, nt in 2x2 of 128x128).
//            Race-free 3-stage cp.async pipeline (validated R11 ordering).
//            Partials to g_part[split<<16] in full 256x256 layout.
//   Sync:    threadfence + atomic arrival + bounded spin (all 128 CTAs are
//            co-resident: 110KB smem -> 1 CTA/SM, 128 <= 148 SMs).
//   Phase 2: CTA bid handles anchors 2bid, 2bid+1. G row reduced on the fly
//            from the 32 split partials (coalesced 1KB rows). sq from g_sqp.
//            Impostor-major loss (validated R7 logic), float warp reduce,
//            fp64 only at CTA/grid combination. Last-CTA election finishes.
// ---------------------------------------------------------------------------
extern __shared__ unsigned char dsm[];

__global__ __launch_bounds__(256, 1) void fused_kernel(const int* __restrict__ mods,
                                                       float* __restrict__ out) {
    const int bid  = blockIdx.x;
    const int t    = threadIdx.x;
    const int w    = t >> 5;
    const int lane = t & 31;
    const int wm   = w >> 2;
    const int wn   = w & 3;
    const uint32_t sb = smem_u32(dsm);

    // ---------------- Phase 1: GEMM ----------------
    const int split = bid & 31;
    const int tile  = bid >> 5;
    const int mt    = tile & 1;
    const int nt    = tile >> 1;
    const int chunk0 = split * CHUNK;

    const __half* gA = g_h + (size_t)(mt * 128) * DIM + chunk0;
    const __half* gB = g_h + (size_t)(nt * 128) * DIM + chunk0;

    float acc[4][4][4];
#pragma unroll
    for (int i = 0; i < 4; i++)
#pragma unroll
        for (int j = 0; j < 4; j++)
#pragma unroll
            for (int r = 0; r < 4; r++) acc[i][j][r] = 0.f;

    auto issue = [&](int kb, int st_idx) {
        const uint32_t st = sb + st_idx * STAGE;
        const int kcol = kb * KB;
#pragma unroll
        for (int i = 0; i < 8; i++) {
            const int idx = t + 256 * i;
            const int ab  = idx >> 10;
            const int s2  = idx & 1023;
            const int row = s2 >> 3;
            const int c   = s2 & 7;
            const __half* gp = (ab ? gB : gA) + (size_t)row * DIM + kcol + c * 8;
            cpasync16(st + ab * TILE_SM + row * STRIDE + c * 16, gp);
        }
        asm volatile("cp.async.commit_group;" ::: "memory");
    };

    issue(0, 0);
    issue(1, 1);

    const uint32_t a_ld = (uint32_t)(wm * 64 + (lane & 15)) * STRIDE + ((lane >> 4) & 1) * 16;
    const int bsel  = (lane >> 3) & 3;
    const uint32_t b_ld = (uint32_t)(wn * 32 + ((bsel >> 1) * 8) + (lane & 7)) * STRIDE
                        + (bsel & 1) * 16;

    for (int ii = 0; ii < WPC; ii++) {
        const int st_idx = ii % NSTAGE;
        if (ii + 1 < WPC) {
            asm volatile("cp.async.wait_group 1;" ::: "memory");
        } else {
            asm volatile("cp.async.wait_group 0;" ::: "memory");
        }
        __syncthreads();   // reads of stage (ii-1) retired; stage st_idx ready
        if (ii + 2 < WPC) issue(ii + 2, (ii + 2) % NSTAGE);

        const uint32_t st = sb + st_idx * STAGE;
#pragma unroll
        for (int ks = 0; ks < 4; ks++) {
            const uint32_t ko = ks * 32;
            uint32_t af[4][4];
#pragma unroll
            for (int i = 0; i < 4; i++)
                ldm_x4(st + a_ld + (uint32_t)i * 16 * STRIDE + ko,
                       af[i][0], af[i][1], af[i][2], af[i][3]);
            uint32_t bf[2][4];
#pragma unroll
            for (int p = 0; p < 2; p++)
                ldm_x4(st + TILE_SM + b_ld + (uint32_t)p * 16 * STRIDE + ko,
                       bf[p][0], bf[p][1], bf[p][2], bf[p][3]);
#pragma unroll
            for (int i = 0; i < 4; i++)
#pragma unroll
                for (int j = 0; j < 4; j++) {
                    const int p = j >> 1, h = (j & 1) * 2;
                    mma16816(acc[i][j][0], acc[i][j][1], acc[i][j][2], acc[i][j][3],
                             af[i][0], af[i][1], af[i][2], af[i][3],
                             bf[p][h], bf[p][h + 1]);
                }
        }
    }

    // flush partial tile to g_part[split] in full 256x256 layout
    {
        float* o = g_part + ((size_t)split << 16);
        const int rb = mt * 128 + wm * 64 + (lane >> 2);
        const int cb = nt * 128 + wn * 32 + (lane & 3) * 2;
#pragma unroll
        for (int i = 0; i < 4; i++)
#pragma unroll
            for (int j = 0; j < 4; j++) {
                const int r0 = rb + i * 16;
                const int c  = cb + j * 8;
                *reinterpret_cast<float2*>(o + r0 * BB + c)       = make_float2(acc[i][j][0], acc[i][j][1]);
                *reinterpret_cast<float2*>(o + (r0 + 8) * BB + c) = make_float2(acc[i][j][2], acc[i][j][3]);
            }
    }

    // ---------------- grid spin-sync (all CTAs co-resident) ----------------
    __threadfence();
    if (t == 0) {
        atomicAdd(&g_sync1, 1);
        long long it = 0;
        while (*(volatile int*)&g_sync1 < NCTA && it < (1LL << 28)) it++;
    }
    __syncthreads();
    __threadfence();

    // ---------------- Phase 2: loss ----------------
    int*    smod = reinterpret_cast<int*>(dsm);            // 1 KB
    float*  sqs  = reinterpret_cast<float*>(dsm + 1024);   // 1 KB
    float*  pv   = reinterpret_cast<float*>(dsm + 2048);   // 1.1 KB
    int*    wpos = reinterpret_cast<int*>(dsm + 3200);
    int*    wimp = reinterpret_cast<int*>(dsm + 3264);
    float*  warr = reinterpret_cast<float*>(dsm + 3328);
    double* sL   = reinterpret_cast<double*>(dsm + 3456);  // 1 KB (final tree)
    double* sC   = reinterpret_cast<double*>(dsm + 4480);  // 1 KB
    __shared__ int is_last;

    smod[t] = mods[t];
    {
        const float* qp = g_sqp + t * 16;
        float ssum = 0.f;
#pragma unroll
        for (int i = 0; i < 16; i++) ssum += qp[i];
        sqs[t] = ssum;
    }
    __syncthreads();

    double lossAcc = 0.0, cntAcc = 0.0;
#pragma unroll 1
    for (int ai = 0; ai < 2; ai++) {
        const int a  = bid * 2 + ai;
        const int ma = smod[a];

        // reduce G[a, t] from the 32 split partials (coalesced rows)
        float gv = 0.f;
        const float* rp = g_part + a * BB + t;
#pragma unroll
        for (int p = 0; p < SPLITS; p++) gv += rp[(size_t)p << 16];

        float d2 = fmaxf(sqs[a] + sqs[t] - 2.f * gv, 0.f);
        const float dv = (d2 > 0.f) ? sqrtf(d2) : 0.f;

        const bool imp = (smod[t] != ma);
        const bool pos = (t != a) && !imp;

        const uint32_t bp = __ballot_sync(0xFFFFFFFFu, pos);
        const uint32_t bi = __ballot_sync(0xFFFFFFFFu, imp);
        if (lane == 0) { wpos[w] = __popc(bp); wimp[w] = __popc(bi); }
        __syncthreads();

        int base = 0, nPos = 0, nImp = 0;
#pragma unroll
        for (int i = 0; i < 8; i++) {
            if (i < w) base += wpos[i];
            nPos += wpos[i];
            nImp += wimp[i];
        }
        if (pos) pv[base + __popc(bp & ((1u << lane) - 1u))] = dv + MARGIN;
        if (t < 8) pv[nPos + t] = -1e30f;   // padding: relu self-masks
        __syncthreads();

        float a0 = 0.f, a1 = 0.f;
        if (imp) {
            const float dak = dv;
            const int n8 = (nPos + 7) & ~7;
#pragma unroll 1
            for (int i = 0; i < n8; i += 8) {
                a0 += fmaxf(pv[i + 0] - dak, 0.f);
                a1 += fmaxf(pv[i + 1] - dak, 0.f);
                a0 += fmaxf(pv[i + 2] - dak, 0.f);
                a1 += fmaxf(pv[i + 3] - dak, 0.f);
                a0 += fmaxf(pv[i + 4] - dak, 0.f);
                a1 += fmaxf(pv[i + 5] - dak, 0.f);
                a0 += fmaxf(pv[i + 6] - dak, 0.f);
                a1 += fmaxf(pv[i + 7] - dak, 0.f);
            }
        }
        float s = a0 + a1;
#pragma unroll
        for (int o = 16; o > 0; o >>= 1) s += __shfl_xor_sync(0xFFFFFFFFu, s, o);
        if (lane == 0) warr[w] = s;
        __syncthreads();
        if (t == 0) {
            double bs = 0.0;
#pragma unroll
            for (int i = 0; i < 8; i++) bs += (double)warr[i];
            lossAcc += bs;
            cntAcc  += (double)nPos * (double)nImp;
        }
        __syncthreads();   // pv/warr reuse safe for next anchor
    }

    if (t == 0) { g_lossp[bid] = lossAcc; g_cntp[bid] = cntAcc; }

    // ---------------- last-CTA election + final reduce ----------------
    __threadfence();
    if (t == 0) {
        int old = atomicAdd(&g_elect, 1);
        is_last = (old == NCTA - 1);
    }
    __syncthreads();
    if (is_last) {
        __threadfence();
        if (t < NCTA) { sL[t] = g_lossp[t]; sC[t] = g_cntp[t]; }
        __syncthreads();
        for (int stride = 64; stride > 0; stride >>= 1) {
            if (t < stride) { sL[t] += sL[t + stride]; sC[t] += sC[t + stride]; }
            __syncthreads();
        }
        if (t == 0) out[0] = (float)(sL[0] / sC[0]);
    }
}

// ---------------------------------------------------------------------------
extern "C" void kernel_launch(void* const* d_in, const int* in_sizes, int n_in,
                              void* d_out, int out_size) {
    const float* X    = (const float*)d_in[0];
    const int*   mods = (const int*)  d_in[1];
    (void)in_sizes; (void)n_in; (void)out_size;

    cudaFuncSetAttribute(fused_kernel, cudaFuncAttributeMaxDynamicSharedMemorySize, SMEM_TOTAL);

    convert_kernel<<<(BB * DIM / 8) / 256, 256>>>(X);
    fused_kernel<<<NCTA, 256, SMEM_TOTAL>>>(mods, (float*)d_out);
}

// round 14
// speedup vs baseline: 1.0251x; 1.0251x over previous
#include <cuda_runtime.h>
#include <cuda_fp16.h>
#include <math.h>
#include <stdint.h>

// ---------------------------------------------------------------------------
// Problem constants
// ---------------------------------------------------------------------------
#define BB       256
#define DIM      32768
#define SPLITS   64
#define CHUNK    (DIM / SPLITS)     // 512 fp16 cols per split
#define KB       32                 // k-block = 64 B/row
#define WPC      (CHUNK / KB)       // 16 k-blocks per CTA
#define STRIDE   80                 // smem row stride (64 B data + 16 B pad)
#define TILE_SM  (128 * STRIDE)     // 10240 B
#define STAGE    (2 * TILE_SM)      // 20480 B
#define NSTAGE   3
#define SMEM_TOTAL (NSTAGE * STAGE) // 61440 B -> 2 CTAs/SM
#define MARGIN   0.003f

// ---------------------------------------------------------------------------
// Static device scratch (no allocations anywhere)
// ---------------------------------------------------------------------------
__device__ __align__(16) __half g_h[BB * DIM];       // 16 MB fp16 copy of X
__device__ float  g_part[SPLITS * BB * BB];          // 16 MB split-K partials
__device__ float  g_sqp[4096];                       // per-block sum-of-squares partials
__device__ double g_lossp[BB];
__device__ double g_cntp[BB];
__device__ int    g_count;

// ---------------------------------------------------------------------------
// Helpers
// ---------------------------------------------------------------------------
__device__ __forceinline__ uint32_t smem_u32(const void* p) {
    uint32_t a;
    asm("{ .reg .u64 t; cvta.to.shared.u64 t, %1; cvt.u32.u64 %0, t; }" : "=r"(a) : "l"(p));
    return a;
}
__device__ __forceinline__ void cpasync16(uint32_t s, const void* g) {
    asm volatile("cp.async.cg.shared.global [%0], [%1], 16;" :: "r"(s), "l"(g) : "memory");
}
__device__ __forceinline__ void ldm_x4(uint32_t a, uint32_t& r0, uint32_t& r1,
                                       uint32_t& r2, uint32_t& r3) {
    asm volatile("ldmatrix.sync.aligned.m8n8.x4.shared.b16 {%0,%1,%2,%3}, [%4];"
                 : "=r"(r0), "=r"(r1), "=r"(r2), "=r"(r3) : "r"(a));
}
__device__ __forceinline__ void mma16816(float& c0, float& c1, float& c2, float& c3,
                                         uint32_t a0, uint32_t a1, uint32_t a2, uint32_t a3,
                                         uint32_t b0, uint32_t b1) {
    asm volatile(
        "mma.sync.aligned.m16n8k16.row.col.f32.f16.f16.f32 "
        "{%0,%1,%2,%3}, {%4,%5,%6,%7}, {%8,%9}, {%0,%1,%2,%3};"
        : "+f"(c0), "+f"(c1), "+f"(c2), "+f"(c3)
        : "r"(a0), "r"(a1), "r"(a2), "r"(a3), "r"(b0), "r"(b1));
}

// ---------------------------------------------------------------------------
// Kernel 1: fp32 -> fp16 convert + exact fp32 sum-of-squares partials.
// Block b covers 2048 contiguous elements (row b/16, part b%16).
// Also resets g_count (stream order precedes the loss kernel).
// ---------------------------------------------------------------------------
__global__ __launch_bounds__(256) void convert_kernel(const float* __restrict__ X) {
    const int b   = blockIdx.x;
    const int t   = threadIdx.x;
    const int gid = b * 256 + t;
    __shared__ float warr[8];

    const float4* s = reinterpret_cast<const float4*>(X) + (size_t)gid * 2;
    const float4 a = s[0];
    const float4 c = s[1];
    __half2 h0 = __floats2half2_rn(a.x, a.y);
    __half2 h1 = __floats2half2_rn(a.z, a.w);
    __half2 h2 = __floats2half2_rn(c.x, c.y);
    __half2 h3 = __floats2half2_rn(c.z, c.w);
    uint4 v;
    v.x = *reinterpret_cast<uint32_t*>(&h0);
    v.y = *reinterpret_cast<uint32_t*>(&h1);
    v.z = *reinterpret_cast<uint32_t*>(&h2);
    v.w = *reinterpret_cast<uint32_t*>(&h3);
    reinterpret_cast<uint4*>(g_h)[gid] = v;

    float sq = a.x * a.x + a.y * a.y + a.z * a.z + a.w * a.w
             + c.x * c.x + c.y * c.y + c.z * c.z + c.w * c.w;
#pragma unroll
    for (int o = 16; o > 0; o >>= 1) sq += __shfl_xor_sync(0xFFFFFFFFu, sq, o);
    if ((t & 31) == 0) warr[t >> 5] = sq;
    __syncthreads();
    if (t == 0) {
        float ssum = 0.f;
#pragma unroll
        for (int i = 0; i < 8; i++) ssum += warr[i];
        g_sqp[b] = ssum;
    }
    if (b == 0 && t == 0) g_count = 0;
}

// ---------------------------------------------------------------------------
// Kernel 2: split-K fp16 GEMM, 2 CTAs/SM (60 KB smem, <=128 regs).
//   grid (SPLITS, 4): blockIdx.y -> (mt, nt) 2x2 tiles of 128x128.
//   KB=32 k-blocks, 3-stage cp.async ring, race-free prefetch ordering
//   (issue after the barrier that retires the previous readers).
// ---------------------------------------------------------------------------
extern __shared__ unsigned char dsm[];

__global__ __launch_bounds__(256, 2) void gemm_kernel() {
    const int split = blockIdx.x;
    const int mt = blockIdx.y & 1;
    const int nt = blockIdx.y >> 1;
    const int t    = threadIdx.x;
    const int w    = t >> 5;
    const int lane = t & 31;
    const int wm   = w >> 2;
    const int wn   = w & 3;

    const uint32_t sb = smem_u32(dsm);
    const int chunk0 = split * CHUNK;

    const __half* gA = g_h + (size_t)(mt * 128) * DIM + chunk0;
    const __half* gB = g_h + (size_t)(nt * 128) * DIM + chunk0;

    float acc[4][4][4];
#pragma unroll
    for (int i = 0; i < 4; i++)
#pragma unroll
        for (int j = 0; j < 4; j++)
#pragma unroll
            for (int r = 0; r < 4; r++) acc[i][j][r] = 0.f;

    // per k-block: 2 tiles x 128 rows x 4 x 16B segs = 1024 segs, 4 per thread
    auto issue = [&](int kb, int st_idx) {
        const uint32_t st = sb + st_idx * STAGE;
        const int kcol = kb * KB;
#pragma unroll
        for (int i = 0; i < 4; i++) {
            const int idx = t + 256 * i;
            const int ab  = idx >> 9;        // 0 = A, 1 = B
            const int s2  = idx & 511;
            const int row = s2 >> 2;
            const int c   = s2 & 3;
            const __half* gp = (ab ? gB : gA) + (size_t)row * DIM + kcol + c * 8;
            cpasync16(st + ab * TILE_SM + row * STRIDE + c * 16, gp);
        }
        asm volatile("cp.async.commit_group;" ::: "memory");
    };

    issue(0, 0);
    issue(1, 1);

    const uint32_t a_ld = (uint32_t)(wm * 64 + (lane & 15)) * STRIDE + ((lane >> 4) & 1) * 16;
    const int bsel  = (lane >> 3) & 3;
    const uint32_t b_ld = (uint32_t)(wn * 32 + ((bsel >> 1) * 8) + (lane & 7)) * STRIDE
                        + (bsel & 1) * 16;

    for (int ii = 0; ii < WPC; ii++) {
        const int st_idx = ii % NSTAGE;
        if (ii + 1 < WPC) {
            asm volatile("cp.async.wait_group 1;" ::: "memory");
        } else {
            asm volatile("cp.async.wait_group 0;" ::: "memory");
        }
        __syncthreads();   // reads of stage (ii-1) retired; stage st_idx ready
        if (ii + 2 < WPC) issue(ii + 2, (ii + 2) % NSTAGE);

        const uint32_t st = sb + st_idx * STAGE;
#pragma unroll
        for (int ks = 0; ks < 2; ks++) {
            const uint32_t ko = ks * 32;
            uint32_t af[4][4];
#pragma unroll
            for (int i = 0; i < 4; i++)
                ldm_x4(st + a_ld + (uint32_t)i * 16 * STRIDE + ko,
                       af[i][0], af[i][1], af[i][2], af[i][3]);
            uint32_t bf[2][4];
#pragma unroll
            for (int p = 0; p < 2; p++)
                ldm_x4(st + TILE_SM + b_ld + (uint32_t)p * 16 * STRIDE + ko,
                       bf[p][0], bf[p][1], bf[p][2], bf[p][3]);
#pragma unroll
            for (int i = 0; i < 4; i++)
#pragma unroll
                for (int j = 0; j < 4; j++) {
                    const int p = j >> 1, h = (j & 1) * 2;
                    mma16816(acc[i][j][0], acc[i][j][1], acc[i][j][2], acc[i][j][3],
                             af[i][0], af[i][1], af[i][2], af[i][3],
                             bf[p][h], bf[p][h + 1]);
                }
        }
    }

    float* out = g_part + ((size_t)split << 16);
    const int rbase = mt * 128 + wm * 64 + (lane >> 2);
    const int cbase = nt * 128 + wn * 32 + (lane & 3) * 2;
#pragma unroll
    for (int i = 0; i < 4; i++)
#pragma unroll
        for (int j = 0; j < 4; j++) {
            const int r0 = rbase + i * 16;
            const int c  = cbase + j * 8;
            *reinterpret_cast<float2*>(out + r0 * BB + c)       = make_float2(acc[i][j][0], acc[i][j][1]);
            *reinterpret_cast<float2*>(out + (r0 + 8) * BB + c) = make_float2(acc[i][j][2], acc[i][j][3]);
        }
}

// ---------------------------------------------------------------------------
// Kernel 3: loss, block-per-anchor, G-row reduced on the fly from the 64
// split partials (coalesced, 8-way batched for MLP). Exact fp32 norms from
// g_sqp. Impostor-major inner loop (validated R7), fused final reduction.
// ---------------------------------------------------------------------------
__global__ __launch_bounds__(256) void loss_kernel(const int* __restrict__ mods,
                                                   float* __restrict__ out) {
    const int a = blockIdx.x;
    const int t = threadIdx.x;
    const int w = t >> 5;
    const int lane = t & 31;
    __shared__ int    smod[BB];
    __shared__ float  sqs[BB];
    __shared__ float  pv[BB + 8];
    __shared__ int    wpos[8], wimp[8];
    __shared__ double dacc[BB];
    __shared__ int    is_last;

    smod[t] = mods[t];
    {
        const float* qp = g_sqp + t * 16;
        float ssum = 0.f;
#pragma unroll
        for (int i = 0; i < 16; i++) ssum += qp[i];
        sqs[t] = ssum;
    }
    __syncthreads();

    // reduce G[a, t] over 64 splits (stride 64K floats; coalesced across t)
    float gv;
    {
        const float* rp = g_part + a * BB + t;
        float s0 = 0.f, s1 = 0.f, s2 = 0.f, s3 = 0.f;
        float s4 = 0.f, s5 = 0.f, s6 = 0.f, s7 = 0.f;
#pragma unroll
        for (int p = 0; p < SPLITS; p += 8) {
            s0 += rp[(size_t)(p + 0) << 16];
            s1 += rp[(size_t)(p + 1) << 16];
            s2 += rp[(size_t)(p + 2) << 16];
            s3 += rp[(size_t)(p + 3) << 16];
            s4 += rp[(size_t)(p + 4) << 16];
            s5 += rp[(size_t)(p + 5) << 16];
            s6 += rp[(size_t)(p + 6) << 16];
            s7 += rp[(size_t)(p + 7) << 16];
        }
        gv = ((s0 + s1) + (s2 + s3)) + ((s4 + s5) + (s6 + s7));
    }

    const int ma = smod[a];
    float d2 = fmaxf(sqs[a] + sqs[t] - 2.f * gv, 0.f);
    const float dv = (d2 > 0.f) ? sqrtf(d2) : 0.f;

    const bool imp = (smod[t] != ma);
    const bool pos = (t != a) && !imp;

    const uint32_t bp = __ballot_sync(0xFFFFFFFFu, pos);
    const uint32_t bi = __ballot_sync(0xFFFFFFFFu, imp);
    if (lane == 0) { wpos[w] = __popc(bp); wimp[w] = __popc(bi); }
    __syncthreads();

    int base = 0, nPos = 0, nImp = 0;
#pragma unroll
    for (int i = 0; i < 8; i++) {
        if (i < w) base += wpos[i];
        nPos += wpos[i];
        nImp += wimp[i];
    }
    if (pos) pv[base + __popc(bp & ((1u << lane) - 1u))] = dv + MARGIN;
    if (t < 8) pv[nPos + t] = -1e30f;   // padding: relu self-masks
    __syncthreads();

    float a0 = 0.f, a1 = 0.f;
    if (imp) {
        const float dak = dv;
        const int n8 = (nPos + 7) & ~7;
#pragma unroll 1
        for (int i = 0; i < n8; i += 8) {
            a0 += fmaxf(pv[i + 0] - dak, 0.f);
            a1 += fmaxf(pv[i + 1] - dak, 0.f);
            a0 += fmaxf(pv[i + 2] - dak, 0.f);
            a1 += fmaxf(pv[i + 3] - dak, 0.f);
            a0 += fmaxf(pv[i + 4] - dak, 0.f);
            a1 += fmaxf(pv[i + 5] - dak, 0.f);
            a0 += fmaxf(pv[i + 6] - dak, 0.f);
            a1 += fmaxf(pv[i + 7] - dak, 0.f);
        }
    }
    dacc[t] = (double)(a0 + a1);
    __syncthreads();
    for (int stride = 128; stride > 0; stride >>= 1) {
        if (t < stride) dacc[t] += dacc[t + stride];
        __syncthreads();
    }
    if (t == 0) {
        g_lossp[a] = dacc[0];
        g_cntp[a]  = (double)nPos * (double)nImp;
    }

    __threadfence();
    if (t == 0) {
        int old = atomicAdd(&g_count, 1);
        is_last = (old == BB - 1);
    }
    __syncthreads();
    if (is_last) {
        __threadfence();
        __shared__ double scnt2[BB];
        dacc[t]  = g_lossp[t];
        scnt2[t] = g_cntp[t];
        __syncthreads();
        for (int stride = 128; stride > 0; stride >>= 1) {
            if (t < stride) { dacc[t] += dacc[t + stride]; scnt2[t] += scnt2[t + stride]; }
            __syncthreads();
        }
        if (t == 0) out[0] = (float)(dacc[0] / scnt2[0]);
    }
}

// ---------------------------------------------------------------------------
extern "C" void kernel_launch(void* const* d_in, const int* in_sizes, int n_in,
                              void* d_out, int out_size) {
    const float* X    = (const float*)d_in[0];
    const int*   mods = (const int*)  d_in[1];
    (void)in_sizes; (void)n_in; (void)out_size;

    cudaFuncSetAttribute(gemm_kernel, cudaFuncAttributeMaxDynamicSharedMemorySize, SMEM_TOTAL);

    convert_kernel<<<(BB * DIM / 8) / 256, 256>>>(X);
    gemm_kernel<<<dim3(SPLITS, 4), 256, SMEM_TOTAL>>>();
    loss_kernel<<<BB, 256>>>(mods, (float*)d_out);
}